// round 7
// baseline (speedup 1.0000x reference)
#include <cuda_runtime.h>
#include <math.h>

#define N_MAX 16384
#define D 16
#define TBLOCK 256
#define T_EVAL 4
#define EVAL_PER_BLOCK (TBLOCK * T_EVAL)   // 1024 eval rows per block
#define NSPLIT 32
#define BTILE 128

// Scratch (no device allocation allowed): per-base constants + split partials.
__device__ float g_cb[N_MAX];
__device__ float g_part[NSPLIT * N_MAX];

// t1 = -0.5*D*log(2*pi) - log(0.1)
#define T1_CONST (-12.400431438280716f)

__global__ void kde_prep_cb(const float* __restrict__ xb, int n) {
    int j = blockIdx.x * blockDim.x + threadIdx.x;
    if (j < n) {
        const float4* r = (const float4*)(xb + (size_t)j * D);
        float s = 0.f;
        #pragma unroll
        for (int q = 0; q < 4; q++) {
            float4 v = r[q];
            s += v.x * v.x + v.y * v.y + v.z * v.z + v.w * v.w;
        }
        g_cb[j] = -50.0f * s;
    }
}

__global__ __launch_bounds__(TBLOCK) void kde_main(const float* __restrict__ xe,
                                                   const float* __restrict__ xb,
                                                   int n) {
    __shared__ float sb[BTILE * D];
    __shared__ float scb[BTILE];

    const int split = blockIdx.y;
    const int base_per_split = n / NSPLIT;
    const int base0 = split * base_per_split;
    const int base1 = base0 + base_per_split;
    const int erow0 = blockIdx.x * EVAL_PER_BLOCK + threadIdx.x * T_EVAL;

    // Load this thread's 4 eval rows, pre-scaled by 100 (so dot accumulates 100*<e,b>),
    // and the per-row constant ce = t1 - 50*||e||^2.
    float se[T_EVAL][D];
    float ce[T_EVAL];
    float acc[T_EVAL];
    #pragma unroll
    for (int t = 0; t < T_EVAL; t++) {
        const float4* r = (const float4*)(xe + (size_t)(erow0 + t) * D);
        float e2 = 0.f;
        #pragma unroll
        for (int q = 0; q < 4; q++) {
            float4 v = r[q];
            e2 += v.x * v.x + v.y * v.y + v.z * v.z + v.w * v.w;
            se[t][4 * q + 0] = 100.f * v.x;
            se[t][4 * q + 1] = 100.f * v.y;
            se[t][4 * q + 2] = 100.f * v.z;
            se[t][4 * q + 3] = 100.f * v.w;
        }
        ce[t] = T1_CONST - 50.f * e2;
        acc[t] = 0.f;
    }

    for (int tb = base0; tb < base1; tb += BTILE) {
        __syncthreads();
        // Stage BTILE base rows (2048 floats) + their cb constants into smem.
        #pragma unroll
        for (int idx = threadIdx.x; idx < BTILE * D / 4; idx += TBLOCK)
            ((float4*)sb)[idx] = ((const float4*)(xb + (size_t)tb * D))[idx];
        if (threadIdx.x < BTILE)
            scb[threadIdx.x] = g_cb[tb + threadIdx.x];
        __syncthreads();

        #pragma unroll 2
        for (int j = 0; j < BTILE; j++) {
            float b[D];
            #pragma unroll
            for (int q = 0; q < 4; q++) {
                float4 v = ((const float4*)(sb + j * D))[q];  // warp-broadcast LDS
                b[4 * q + 0] = v.x; b[4 * q + 1] = v.y;
                b[4 * q + 2] = v.z; b[4 * q + 3] = v.w;
            }
            const float cbj = scb[j];
            #pragma unroll
            for (int t = 0; t < T_EVAL; t++) {
                float s = ce[t] + cbj;              // s = t1 - 50*(e2+b2) + 100*dot (accumulated below)
                #pragma unroll
                for (int k = 0; k < D; k++)
                    s = fmaf(se[t][k], b[k], s);
                // expf underflows to 0 below -87.3; contributions in (-87,-30) are
                // < N*exp(-30)/N = 1e-13 << eps, so this guard is exact.
                if (s > -87.0f)
                    acc[t] += __expf(s);
            }
        }
    }

    #pragma unroll
    for (int t = 0; t < T_EVAL; t++)
        g_part[(size_t)split * n + (erow0 + t)] = acc[t];
}

__global__ void kde_reduce(float* __restrict__ out, int n) {
    int i = blockIdx.x * blockDim.x + threadIdx.x;
    if (i < n) {
        float s = 0.f;
        #pragma unroll
        for (int k = 0; k < NSPLIT; k++)
            s += g_part[(size_t)k * n + i];
        out[i] = logf(1e-8f + s * (1.0f / (float)n));
    }
}

extern "C" void kernel_launch(void* const* d_in, const int* in_sizes, int n_in,
                              void* d_out, int out_size) {
    const float* x_eval = (const float*)d_in[0];
    const float* x_base = (const float*)d_in[1];
    float* out = (float*)d_out;
    const int n = in_sizes[0] / D;   // 16384

    kde_prep_cb<<<(n + 255) / 256, 256>>>(x_base, n);
    dim3 grid(n / EVAL_PER_BLOCK, NSPLIT);
    kde_main<<<grid, TBLOCK>>>(x_eval, x_base, n);
    kde_reduce<<<(n + 255) / 256, 256>>>(out, n);
}

// round 8
// speedup vs baseline: 1.1259x; 1.1259x over previous
#include <cuda_runtime.h>
#include <math.h>

#define N_MAX 16384
#define D 16
#define TBLOCK 256
#define T_EVAL 4
#define EVAL_PER_BLOCK (TBLOCK * T_EVAL)   // 1024 eval rows per block -> 16 x-blocks
#define NSPLIT 37                          // 16*37 = 592 = 4*148 blocks: perfect SM balance
#define BTILE 128

typedef unsigned long long ull;

// Scratch (no device allocation allowed): per-base constants + split partials.
__device__ float g_cb[N_MAX];
__device__ float g_part[NSPLIT * N_MAX];

// t1 = -0.5*D*log(2*pi) - log(0.1)
#define T1_CONST (-12.400431438280716f)

// Packed f32x2 FMA: d = a*b + c lanewise (one FFMA2, 2 FMAs/instr on sm_103a).
#define FMA2(d, a, b, c) \
    asm("fma.rn.f32x2 %0, %1, %2, %3;" : "=l"(d) : "l"(a), "l"(b), "l"(c))
#define PACK2(out, lo, hi) \
    asm("mov.b64 %0, {%1, %2};" : "=l"(out) : "r"(lo), "r"(hi))
#define UNPACK2(lo, hi, in) \
    asm("mov.b64 {%0, %1}, %2;" : "=r"(lo), "=r"(hi) : "l"(in))

__global__ void kde_prep_cb(const float* __restrict__ xb, int n) {
    int j = blockIdx.x * blockDim.x + threadIdx.x;
    if (j < n) {
        const float4* r = (const float4*)(xb + (size_t)j * D);
        float s = 0.f;
        #pragma unroll
        for (int q = 0; q < 4; q++) {
            float4 v = r[q];
            s += v.x * v.x + v.y * v.y + v.z * v.z + v.w * v.w;
        }
        g_cb[j] = -50.0f * s;
    }
}

__global__ __launch_bounds__(TBLOCK) void kde_main(const float* __restrict__ xe,
                                                   const float* __restrict__ xb,
                                                   int n) {
    __shared__ float sb[BTILE * D];
    __shared__ float scb[BTILE];

    const int split = blockIdx.y;
    const int split_sz = (n + NSPLIT - 1) / NSPLIT;          // 443
    const int base0 = split * split_sz;
    const int base1 = min(n, base0 + split_sz);
    const int erow0 = blockIdx.x * EVAL_PER_BLOCK + threadIdx.x * T_EVAL;

    // Per-thread eval rows: se packed as f32x2 pairs (pre-scaled by 100 so the
    // packed dot accumulates 100*<e,b>); ce2 = (t1 - 50*||e||^2, 0) packed so it
    // seeds the lo lane of the accumulator for free.
    ull se2[T_EVAL][D / 2];
    ull ce2[T_EVAL];
    float acc[T_EVAL];
    #pragma unroll
    for (int t = 0; t < T_EVAL; t++) {
        const float4* r = (const float4*)(xe + (size_t)(erow0 + t) * D);
        float e2 = 0.f;
        #pragma unroll
        for (int q = 0; q < 4; q++) {
            float4 v = r[q];
            e2 += v.x * v.x + v.y * v.y + v.z * v.z + v.w * v.w;
            float sx = 100.f * v.x, sy = 100.f * v.y;
            float sz = 100.f * v.z, sw = 100.f * v.w;
            PACK2(se2[t][2 * q + 0], __float_as_uint(sx), __float_as_uint(sy));
            PACK2(se2[t][2 * q + 1], __float_as_uint(sz), __float_as_uint(sw));
        }
        float ce = T1_CONST - 50.f * e2;
        PACK2(ce2[t], __float_as_uint(ce), 0u);
        acc[t] = 0.f;
    }

    for (int tb = base0; tb < base1; tb += BTILE) {
        const int jcnt = min(BTILE, base1 - tb);
        __syncthreads();
        // Stage jcnt base rows + their cb constants into smem.
        for (int idx = threadIdx.x; idx < jcnt * (D / 4); idx += TBLOCK)
            ((float4*)sb)[idx] = ((const float4*)(xb + (size_t)tb * D))[idx];
        if (threadIdx.x < jcnt)
            scb[threadIdx.x] = g_cb[tb + threadIdx.x];
        __syncthreads();

        #pragma unroll 2
        for (int j = 0; j < jcnt; j++) {
            // b pairs straight from LDS.128: consecutive regs are valid 64-bit pairs.
            ull b2[D / 2];
            const ulonglong2* bp = (const ulonglong2*)(sb + j * D);
            #pragma unroll
            for (int q = 0; q < 4; q++) {
                ulonglong2 v = bp[q];   // warp-broadcast LDS, conflict-free
                b2[2 * q + 0] = v.x;
                b2[2 * q + 1] = v.y;
            }
            const float cbj = scb[j];
            #pragma unroll
            for (int t = 0; t < T_EVAL; t++) {
                ull a = ce2[t];
                #pragma unroll
                for (int k = 0; k < D / 2; k++)
                    FMA2(a, se2[t][k], b2[k], a);
                unsigned lo_u, hi_u;
                UNPACK2(lo_u, hi_u, a);
                float s = (__uint_as_float(lo_u) + __uint_as_float(hi_u)) + cbj;
                // expf underflows to 0 below -87.3; contributions in (-87,-30) are
                // < exp(-30) = 1e-13 << eps*N, so this guard is exact.
                if (s > -87.0f)
                    acc[t] += __expf(s);
            }
        }
    }

    #pragma unroll
    for (int t = 0; t < T_EVAL; t++)
        g_part[(size_t)split * n + (erow0 + t)] = acc[t];
}

__global__ void kde_reduce(float* __restrict__ out, int n) {
    int i = blockIdx.x * blockDim.x + threadIdx.x;
    if (i < n) {
        float s = 0.f;
        #pragma unroll
        for (int k = 0; k < NSPLIT; k++)
            s += g_part[(size_t)k * n + i];
        out[i] = logf(1e-8f + s * (1.0f / (float)n));
    }
}

extern "C" void kernel_launch(void* const* d_in, const int* in_sizes, int n_in,
                              void* d_out, int out_size) {
    const float* x_eval = (const float*)d_in[0];
    const float* x_base = (const float*)d_in[1];
    float* out = (float*)d_out;
    const int n = in_sizes[0] / D;   // 16384

    kde_prep_cb<<<(n + 255) / 256, 256>>>(x_base, n);
    dim3 grid(n / EVAL_PER_BLOCK, NSPLIT);
    kde_main<<<grid, TBLOCK>>>(x_eval, x_base, n);
    kde_reduce<<<(n + 255) / 256, 256>>>(out, n);
}

// round 10
// speedup vs baseline: 4.0061x; 3.5582x over previous
#include <cuda_runtime.h>
#include <cuda_bf16.h>
#include <math.h>
#include <cstdint>

#define N_PTS 16384
#define D 16
// t1 = -0.5*D*log(2*pi) - log(0.1)
#define T1_CONST (-12.400431438280716f)
#define LOG_EPS  (-18.420680743952367f)   // logf(1e-8)
#define FLAG_THRESH (-45.0f)

#define ROWB 64                 // dense bf16 row bytes in gmem (32 bf16: 20 used + pad)
#define SROWB 80                // smem row stride: 16B-aligned, bank step 5 -> conflict-free
#define BT 128                  // base rows per smem tile
#define NSPLITS 2
#define BT_PER_SPLIT ((N_PTS / NSPLITS) / BT)   // 64

// Scratch (no device allocation allowed)
__device__ unsigned char g_A[N_PTS * ROWB];     // eval rows, bf16 extended
__device__ unsigned char g_B[N_PTS * ROWB];     // base rows, bf16 extended
__device__ float g_rowmax[NSPLITS][N_PTS];

__device__ __forceinline__ uint32_t smem_u32(const void* p) {
    uint32_t a;
    asm("{ .reg .u64 t; cvta.to.shared.u64 t, %1; cvt.u32.u64 %0, t; }" : "=r"(a) : "l"(p));
    return a;
}

#define LDMX4(r0, r1, r2, r3, a) \
    asm volatile("ldmatrix.sync.aligned.m8n8.x4.shared.b16 {%0,%1,%2,%3}, [%4];" \
        : "=r"(r0), "=r"(r1), "=r"(r2), "=r"(r3) : "r"(a))

#define MMA16816(d0,d1,d2,d3, a0,a1,a2,a3, b0,b1, c0,c1,c2,c3) \
    asm volatile("mma.sync.aligned.m16n8k16.row.col.f32.bf16.bf16.f32 " \
        "{%0,%1,%2,%3},{%4,%5,%6,%7},{%8,%9},{%10,%11,%12,%13};" \
        : "=f"(d0), "=f"(d1), "=f"(d2), "=f"(d3) \
        : "r"(a0), "r"(a1), "r"(a2), "r"(a3), "r"(b0), "r"(b1), \
          "f"(c0), "f"(c1), "f"(c2), "f"(c3))

// ---------------- prep: fp32 -> bf16 extended rows (dense 64B rows) ----------------
// A row: [100*e[0..15], ce_hi, ce_lo, 1, 1, 0 x12]   ce = t1 - 50||e||^2  (hi/lo split)
// B row: [b[0..15],     1,     1, cb_hi, cb_lo, 0 x12]  cb = -50||b||^2
// => K=32 dot gives s = 100<e,b> + ce + cb in the fp32 MMA accumulator.
__global__ void kde_prep(const float* __restrict__ xe, const float* __restrict__ xb) {
    int g = blockIdx.x * blockDim.x + threadIdx.x;       // 0..32767
    bool is_e = g < N_PTS;
    int row = is_e ? g : g - N_PTS;
    const float* src = (is_e ? xe : xb) + (size_t)row * D;

    float v[D];
    float n2 = 0.f;
    #pragma unroll
    for (int q = 0; q < 4; q++) {
        float4 t = ((const float4*)src)[q];
        v[4*q+0] = t.x; v[4*q+1] = t.y; v[4*q+2] = t.z; v[4*q+3] = t.w;
        n2 += t.x*t.x + t.y*t.y + t.z*t.z + t.w*t.w;
    }
    float c = is_e ? (T1_CONST - 50.f * n2) : (-50.f * n2);
    __nv_bfloat16 ch = __float2bfloat16(c);
    __nv_bfloat16 cl = __float2bfloat16(c - __bfloat162float(ch));
    __nv_bfloat16 one = __float2bfloat16(1.0f);
    __nv_bfloat16 zero = __float2bfloat16(0.0f);

    __nv_bfloat16 r[32];
    #pragma unroll
    for (int k = 0; k < 16; k++) r[k] = __float2bfloat16(is_e ? 100.f * v[k] : v[k]);
    r[16] = is_e ? ch : one;
    r[17] = is_e ? cl : one;
    r[18] = is_e ? one : ch;
    r[19] = is_e ? one : cl;
    #pragma unroll
    for (int k = 20; k < 32; k++) r[k] = zero;

    uint4* dst = (uint4*)((is_e ? g_A : g_B) + (size_t)row * ROWB);
    const uint4* rp = (const uint4*)r;
    #pragma unroll
    for (int q = 0; q < 4; q++) dst[q] = rp[q];
}

// ---------------- main: HMMA (mma.sync bf16) GEMM + per-row max ----------------
// grid = 256: blockIdx.x = mblk*2 + split. CTA = 128 thr (4 warps), warp owns m32.
__global__ void __launch_bounds__(128) kde_main() {
    __shared__ __align__(16) unsigned char sA[128 * SROWB];
    __shared__ __align__(16) unsigned char sB[2][BT * SROWB];

    const int tid = threadIdx.x, w = tid >> 5, lane = tid & 31;
    const int mblk = blockIdx.x >> 1, split = blockIdx.x & 1;

    // Stage A tile (128 rows) + B tile 0, repadding 64B rows to 80B stride.
    {
        const uint4* Ag = (const uint4*)(g_A + (size_t)mblk * 128 * ROWB);
        const uint4* Bg = (const uint4*)(g_B + (size_t)split * (N_PTS / NSPLITS) * ROWB);
        #pragma unroll
        for (int k = 0; k < 4; k++) {
            int i = tid + k * 128;           // 512 chunks of 16B
            int row = i >> 2, c = i & 3;
            *(uint4*)(sA + row * SROWB + c * 16) = Ag[i];
            *(uint4*)(sB[0] + row * SROWB + c * 16) = Bg[i];
        }
    }
    __syncthreads();

    // A fragments for this warp's 32 rows (2 m16-tiles x 2 k-steps), loaded once.
    const uint32_t sA_a = smem_u32(sA);
    const uint32_t sB_a0 = smem_u32(sB[0]);
    const uint32_t sB_a1 = smem_u32(sB[1]);
    uint32_t af[2][2][4];
    {
        int grp = lane >> 3;
        int arow = ((grp & 1) << 3) + (lane & 7);      // 0..15 within m16 tile
        int akb  = (grp >> 1) << 4;                    // 0 or 16 bytes
        #pragma unroll
        for (int mt = 0; mt < 2; mt++)
            #pragma unroll
            for (int ks = 0; ks < 2; ks++) {
                uint32_t addr = sA_a + (uint32_t)(w * 32 + mt * 16 + arow) * SROWB
                              + (uint32_t)(akb + ks * 32);
                LDMX4(af[mt][ks][0], af[mt][ks][1], af[mt][ks][2], af[mt][ks][3], addr);
            }
    }

    const uint32_t boff = (uint32_t)(lane & 7) * SROWB + (uint32_t)(lane >> 3) * 16;
    const unsigned char* Bg = g_B + (size_t)split * (N_PTS / NSPLITS) * ROWB;
    const float zf = 0.0f;
    float rm[4] = {-3.0e38f, -3.0e38f, -3.0e38f, -3.0e38f};

    for (int t = 0; t < BT_PER_SPLIT; t++) {
        const int cur = t & 1;

        // prefetch next B tile into registers (overlaps compute)
        uint4 nx[4];
        if (t + 1 < BT_PER_SPLIT) {
            const uint4* src = (const uint4*)(Bg + (size_t)(t + 1) * BT * ROWB);
            #pragma unroll
            for (int k = 0; k < 4; k++) nx[k] = src[tid + k * 128];
        }

        const uint32_t bbase = (cur ? sB_a1 : sB_a0) + boff;
        #pragma unroll
        for (int n8 = 0; n8 < 16; n8++) {
            uint32_t b0, b1, b2, b3;
            LDMX4(b0, b1, b2, b3, bbase + (uint32_t)n8 * (8 * SROWB));
            #pragma unroll
            for (int mt = 0; mt < 2; mt++) {
                float d0, d1, d2, d3;
                MMA16816(d0, d1, d2, d3,
                         af[mt][0][0], af[mt][0][1], af[mt][0][2], af[mt][0][3],
                         b0, b1, zf, zf, zf, zf);
                MMA16816(d0, d1, d2, d3,
                         af[mt][1][0], af[mt][1][1], af[mt][1][2], af[mt][1][3],
                         b2, b3, d0, d1, d2, d3);
                rm[mt * 2 + 0] = fmaxf(rm[mt * 2 + 0], fmaxf(d0, d1));
                rm[mt * 2 + 1] = fmaxf(rm[mt * 2 + 1], fmaxf(d2, d3));
            }
        }

        // publish next tile
        if (t + 1 < BT_PER_SPLIT) {
            #pragma unroll
            for (int k = 0; k < 4; k++) {
                int i = tid + k * 128;
                int row = i >> 2, c = i & 3;
                *(uint4*)(sB[cur ^ 1] + row * SROWB + c * 16) = nx[k];
            }
        }
        __syncthreads();
    }

    // reduce across the 4-lane quad (cols of the c fragment), then store row maxes
    #pragma unroll
    for (int i = 0; i < 4; i++) {
        rm[i] = fmaxf(rm[i], __shfl_xor_sync(0xffffffffu, rm[i], 1));
        rm[i] = fmaxf(rm[i], __shfl_xor_sync(0xffffffffu, rm[i], 2));
    }
    if ((lane & 3) == 0) {
        int q = lane >> 2;
        int base = mblk * 128 + w * 32;
        g_rowmax[split][base + q]      = rm[0];
        g_rowmax[split][base + q + 8]  = rm[1];
        g_rowmax[split][base + q + 16] = rm[2];
        g_rowmax[split][base + q + 24] = rm[3];
    }
}

// ---------------- final: exact recompute for flagged rows, const for the rest ----
__global__ void kde_final(const float* __restrict__ xe, const float* __restrict__ xb,
                          float* __restrict__ out) {
    __shared__ int s_list[128];
    __shared__ int s_cnt;
    __shared__ float s_red[128];
    __shared__ float s_e[D];

    int tid = threadIdx.x;
    int row = blockIdx.x * 128 + tid;
    if (tid == 0) s_cnt = 0;
    __syncthreads();

    float mv = fmaxf(g_rowmax[0][row], g_rowmax[1][row]);
    if (mv > FLAG_THRESH) {
        int p = atomicAdd(&s_cnt, 1);
        s_list[p] = row;
    } else {
        out[row] = LOG_EPS;
    }
    __syncthreads();

    for (int f = 0; f < s_cnt; f++) {
        int i = s_list[f];
        if (tid < D) s_e[tid] = xe[(size_t)i * D + tid];
        __syncthreads();
        float e[D];
        #pragma unroll
        for (int k = 0; k < D; k++) e[k] = s_e[k];
        float acc = 0.f;
        for (int j = tid; j < N_PTS; j += 128) {
            const float4* bp = (const float4*)(xb + (size_t)j * D);
            float sq = 0.f;
            #pragma unroll
            for (int q = 0; q < 4; q++) {
                float4 b = bp[q];
                float d0 = e[4*q+0] - b.x, d1 = e[4*q+1] - b.y;
                float d2 = e[4*q+2] - b.z, d3 = e[4*q+3] - b.w;
                sq += d0*d0 + d1*d1 + d2*d2 + d3*d3;
            }
            float s = T1_CONST - 50.f * sq;
            if (s > -87.0f) acc += __expf(s);
        }
        s_red[tid] = acc;
        __syncthreads();
        for (int st = 64; st > 0; st >>= 1) {
            if (tid < st) s_red[tid] += s_red[tid + st];
            __syncthreads();
        }
        if (tid == 0) out[i] = logf(1e-8f + s_red[0] * (1.0f / (float)N_PTS));
        __syncthreads();
    }
}

extern "C" void kernel_launch(void* const* d_in, const int* in_sizes, int n_in,
                              void* d_out, int out_size) {
    const float* x_eval = (const float*)d_in[0];
    const float* x_base = (const float*)d_in[1];
    float* out = (float*)d_out;

    kde_prep<<<(2 * N_PTS) / 256, 256>>>(x_eval, x_base);
    kde_main<<<256, 128>>>();
    kde_final<<<N_PTS / 128, 128>>>(x_eval, x_base, out);
}

// round 11
// speedup vs baseline: 5.3108x; 1.3257x over previous
#include <cuda_runtime.h>
#include <cuda_bf16.h>
#include <math.h>
#include <cstdint>

#define N_PTS 16384
#define D 16
// t1 = -0.5*D*log(2*pi) - log(0.1)
#define T1_CONST (-12.400431438280716f)
#define LOG_EPS  (-18.420680743952367f)   // logf(1e-8)
#define FLAG_THRESH (-45.0f)

#define ROWB 64                 // dense bf16 row bytes in gmem (32 bf16: 20 used + pad)
#define SROWB 80                // smem row stride: 16B-aligned, bank step 5 -> conflict-free
#define BT 128                  // base rows per smem tile
#define NSPLITS 8
#define TILES_PER_SPLIT ((N_PTS / NSPLITS) / BT)   // 16

// Scratch (no device allocation allowed)
__device__ unsigned char g_A[N_PTS * ROWB];     // eval rows, bf16 extended
__device__ unsigned char g_B[N_PTS * ROWB];     // base rows, bf16 extended
__device__ float g_rowmax[NSPLITS][N_PTS];

__device__ __forceinline__ uint32_t smem_u32(const void* p) {
    uint32_t a;
    asm("{ .reg .u64 t; cvta.to.shared.u64 t, %1; cvt.u32.u64 %0, t; }" : "=r"(a) : "l"(p));
    return a;
}

#define LDMX4(r0, r1, r2, r3, a) \
    asm volatile("ldmatrix.sync.aligned.m8n8.x4.shared.b16 {%0,%1,%2,%3}, [%4];" \
        : "=r"(r0), "=r"(r1), "=r"(r2), "=r"(r3) : "r"(a))

#define MMA16816(d0,d1,d2,d3, a0,a1,a2,a3, b0,b1, c0,c1,c2,c3) \
    asm volatile("mma.sync.aligned.m16n8k16.row.col.f32.bf16.bf16.f32 " \
        "{%0,%1,%2,%3},{%4,%5,%6,%7},{%8,%9},{%10,%11,%12,%13};" \
        : "=f"(d0), "=f"(d1), "=f"(d2), "=f"(d3) \
        : "r"(a0), "r"(a1), "r"(a2), "r"(a3), "r"(b0), "r"(b1), \
          "f"(c0), "f"(c1), "f"(c2), "f"(c3))

__device__ __forceinline__ void cp16(uint32_t dst, const void* src) {
    asm volatile("cp.async.cg.shared.global [%0], [%1], 16;" :: "r"(dst), "l"(src));
}
#define CP_COMMIT() asm volatile("cp.async.commit_group;" ::: "memory")
#define CP_WAIT(n)  asm volatile("cp.async.wait_group %0;" :: "n"(n) : "memory")

// ---------------- prep: fp32 -> bf16 extended rows (dense 64B rows) ----------------
// A row: [100*e[0..15], ce_hi, ce_lo, 1, 1, 0 x12]   ce = t1 - 50||e||^2  (hi/lo split)
// B row: [b[0..15],     1,     1, cb_hi, cb_lo, 0 x12]  cb = -50||b||^2
// => K=32 dot gives s = 100<e,b> + ce + cb in the fp32 MMA accumulator.
__global__ void kde_prep(const float* __restrict__ xe, const float* __restrict__ xb) {
    int g = blockIdx.x * blockDim.x + threadIdx.x;       // 0..32767
    bool is_e = g < N_PTS;
    int row = is_e ? g : g - N_PTS;
    const float* src = (is_e ? xe : xb) + (size_t)row * D;

    float v[D];
    float n2 = 0.f;
    #pragma unroll
    for (int q = 0; q < 4; q++) {
        float4 t = ((const float4*)src)[q];
        v[4*q+0] = t.x; v[4*q+1] = t.y; v[4*q+2] = t.z; v[4*q+3] = t.w;
        n2 += t.x*t.x + t.y*t.y + t.z*t.z + t.w*t.w;
    }
    float c = is_e ? (T1_CONST - 50.f * n2) : (-50.f * n2);
    __nv_bfloat16 ch = __float2bfloat16(c);
    __nv_bfloat16 cl = __float2bfloat16(c - __bfloat162float(ch));
    __nv_bfloat16 one = __float2bfloat16(1.0f);
    __nv_bfloat16 zero = __float2bfloat16(0.0f);

    __nv_bfloat16 r[32];
    #pragma unroll
    for (int k = 0; k < 16; k++) r[k] = __float2bfloat16(is_e ? 100.f * v[k] : v[k]);
    r[16] = is_e ? ch : one;
    r[17] = is_e ? cl : one;
    r[18] = is_e ? one : ch;
    r[19] = is_e ? one : cl;
    #pragma unroll
    for (int k = 20; k < 32; k++) r[k] = zero;

    uint4* dst = (uint4*)((is_e ? g_A : g_B) + (size_t)row * ROWB);
    const uint4* rp = (const uint4*)r;
    #pragma unroll
    for (int q = 0; q < 4; q++) dst[q] = rp[q];
}

// ---------------- main: HMMA (mma.sync bf16) GEMM + per-row max ----------------
// grid = 1024: blockIdx.x = mblk*8 + split. CTA = 128 thr (4 warps), warp owns m32.
// ~7 CTAs resident per SM (30 KB smem each) -> ~7 warps/SMSP for latency hiding.
__global__ void __launch_bounds__(128) kde_main() {
    __shared__ __align__(16) unsigned char sA[128 * SROWB];
    __shared__ __align__(16) unsigned char sB[2][BT * SROWB];

    const int tid = threadIdx.x, w = tid >> 5, lane = tid & 31;
    const int mblk = blockIdx.x >> 3, split = blockIdx.x & 7;

    const unsigned char* Ag = g_A + (size_t)mblk * 128 * ROWB;
    const unsigned char* Bg = g_B + (size_t)split * (N_PTS / NSPLITS) * ROWB;

    const uint32_t sA_a  = smem_u32(sA);
    const uint32_t sB_a[2] = { smem_u32(sB[0]), smem_u32(sB[1]) };

    // Prologue (group 0): A tile + B tile 0, repadding 64B rows to 80B smem stride.
    {
        #pragma unroll
        for (int k = 0; k < 4; k++) {
            int i = tid + k * 128;           // 512 chunks of 16B
            uint32_t row = i >> 2, c = i & 3;
            uint32_t soff = row * SROWB + c * 16;
            cp16(sA_a + soff,   Ag + (size_t)i * 16);
            cp16(sB_a[0] + soff, Bg + (size_t)i * 16);
        }
        CP_COMMIT();
        CP_WAIT(0);
    }
    __syncthreads();

    // A fragments for this warp's 32 rows (2 m16-tiles x 2 k-steps), loaded once.
    uint32_t af[2][2][4];
    {
        int grp = lane >> 3;
        int arow = ((grp & 1) << 3) + (lane & 7);      // 0..15 within m16 tile
        int akb  = (grp >> 1) << 4;                    // 0 or 16 bytes
        #pragma unroll
        for (int mt = 0; mt < 2; mt++)
            #pragma unroll
            for (int ks = 0; ks < 2; ks++) {
                uint32_t addr = sA_a + (uint32_t)(w * 32 + mt * 16 + arow) * SROWB
                              + (uint32_t)(akb + ks * 32);
                LDMX4(af[mt][ks][0], af[mt][ks][1], af[mt][ks][2], af[mt][ks][3], addr);
            }
    }

    const uint32_t boff = (uint32_t)(lane & 7) * SROWB + (uint32_t)(lane >> 3) * 16;
    const float zf = 0.0f;
    float rm[4] = {-3.0e38f, -3.0e38f, -3.0e38f, -3.0e38f};

    for (int t = 0; t < TILES_PER_SPLIT; t++) {
        const int cur = t & 1;

        // Issue next tile (group t+1) into the other buffer; it was freed by the
        // trailing __syncthreads() of the previous iteration.
        if (t + 1 < TILES_PER_SPLIT) {
            const unsigned char* src = Bg + (size_t)(t + 1) * BT * ROWB;
            #pragma unroll
            for (int k = 0; k < 4; k++) {
                int i = tid + k * 128;
                uint32_t row = i >> 2, c = i & 3;
                cp16(sB_a[cur ^ 1] + row * SROWB + c * 16, src + (size_t)i * 16);
            }
            CP_COMMIT();
            CP_WAIT(1);          // ensures group t (current tile) is complete
        } else {
            CP_WAIT(0);
        }
        __syncthreads();

        const uint32_t bbase = sB_a[cur] + boff;
        #pragma unroll
        for (int n8 = 0; n8 < 16; n8++) {
            uint32_t b0, b1, b2, b3;
            LDMX4(b0, b1, b2, b3, bbase + (uint32_t)n8 * (8 * SROWB));
            #pragma unroll
            for (int mt = 0; mt < 2; mt++) {
                float d0, d1, d2, d3;
                MMA16816(d0, d1, d2, d3,
                         af[mt][0][0], af[mt][0][1], af[mt][0][2], af[mt][0][3],
                         b0, b1, zf, zf, zf, zf);
                MMA16816(d0, d1, d2, d3,
                         af[mt][1][0], af[mt][1][1], af[mt][1][2], af[mt][1][3],
                         b2, b3, d0, d1, d2, d3);
                rm[mt * 2 + 0] = fmaxf(rm[mt * 2 + 0], fmaxf(d0, d1));
                rm[mt * 2 + 1] = fmaxf(rm[mt * 2 + 1], fmaxf(d2, d3));
            }
        }
        __syncthreads();   // compute on buf[cur] done before group t+2 overwrites it
    }

    // reduce across the 4-lane quad (cols of the c fragment), then store row maxes
    #pragma unroll
    for (int i = 0; i < 4; i++) {
        rm[i] = fmaxf(rm[i], __shfl_xor_sync(0xffffffffu, rm[i], 1));
        rm[i] = fmaxf(rm[i], __shfl_xor_sync(0xffffffffu, rm[i], 2));
    }
    if ((lane & 3) == 0) {
        int q = lane >> 2;
        int base = mblk * 128 + w * 32;
        g_rowmax[split][base + q]      = rm[0];
        g_rowmax[split][base + q + 8]  = rm[1];
        g_rowmax[split][base + q + 16] = rm[2];
        g_rowmax[split][base + q + 24] = rm[3];
    }
}

// ---------------- final: exact recompute for flagged rows, const for the rest ----
__global__ void kde_final(const float* __restrict__ xe, const float* __restrict__ xb,
                          float* __restrict__ out) {
    __shared__ int s_list[128];
    __shared__ int s_cnt;
    __shared__ float s_red[128];
    __shared__ float s_e[D];

    int tid = threadIdx.x;
    int row = blockIdx.x * 128 + tid;
    if (tid == 0) s_cnt = 0;
    __syncthreads();

    float mv = -3.0e38f;
    #pragma unroll
    for (int k = 0; k < NSPLITS; k++) mv = fmaxf(mv, g_rowmax[k][row]);
    if (mv > FLAG_THRESH) {
        int p = atomicAdd(&s_cnt, 1);
        s_list[p] = row;
    } else {
        out[row] = LOG_EPS;
    }
    __syncthreads();

    for (int f = 0; f < s_cnt; f++) {
        int i = s_list[f];
        if (tid < D) s_e[tid] = xe[(size_t)i * D + tid];
        __syncthreads();
        float e[D];
        #pragma unroll
        for (int k = 0; k < D; k++) e[k] = s_e[k];
        float acc = 0.f;
        for (int j = tid; j < N_PTS; j += 128) {
            const float4* bp = (const float4*)(xb + (size_t)j * D);
            float sq = 0.f;
            #pragma unroll
            for (int q = 0; q < 4; q++) {
                float4 b = bp[q];
                float d0 = e[4*q+0] - b.x, d1 = e[4*q+1] - b.y;
                float d2 = e[4*q+2] - b.z, d3 = e[4*q+3] - b.w;
                sq += d0*d0 + d1*d1 + d2*d2 + d3*d3;
            }
            float s = T1_CONST - 50.f * sq;
            if (s > -87.0f) acc += __expf(s);
        }
        s_red[tid] = acc;
        __syncthreads();
        for (int st = 64; st > 0; st >>= 1) {
            if (tid < st) s_red[tid] += s_red[tid + st];
            __syncthreads();
        }
        if (tid == 0) out[i] = logf(1e-8f + s_red[0] * (1.0f / (float)N_PTS));
        __syncthreads();
    }
}

extern "C" void kernel_launch(void* const* d_in, const int* in_sizes, int n_in,
                              void* d_out, int out_size) {
    const float* x_eval = (const float*)d_in[0];
    const float* x_base = (const float*)d_in[1];
    float* out = (float*)d_out;

    kde_prep<<<(2 * N_PTS) / 256, 256>>>(x_eval, x_base);
    kde_main<<<128 * NSPLITS, 128>>>();
    kde_final<<<N_PTS / 128, 128>>>(x_eval, x_base, out);
}

// round 12
// speedup vs baseline: 6.5775x; 1.2385x over previous
#include <cuda_runtime.h>
#include <cuda_bf16.h>
#include <math.h>
#include <cstdint>

#define N_PTS 16384
#define D 16
// t1 = -0.5*D*log(2*pi) - log(0.1)
#define T1_CONST (-12.400431438280716f)
#define LOG_EPS  (-18.420680743952367f)   // logf(1e-8)
#define FLAG_THRESH (-45.0f)

#define ROWB 32                 // dense bf16 row bytes in gmem (16 bf16, K=16 exactly)
#define SROWB 48                // smem row stride: 16B-aligned, 12-bank step -> conflict-free ldmatrix
#define BT 128                  // base rows per smem tile
#define NSPLITS 8
#define TILES_PER_SPLIT ((N_PTS / NSPLITS) / BT)   // 16

// Scratch (no device allocation allowed)
__device__ unsigned char g_A[N_PTS * ROWB];     // eval rows: bf16(100*e)
__device__ unsigned char g_B[N_PTS * ROWB];     // base rows: bf16(b)
__device__ float g_ce[N_PTS];                   // t1 - 50||e||^2   (fp32 exact)
__device__ float g_cb[N_PTS];                   // -50||b||^2       (fp32 exact)
__device__ float g_rowmax[NSPLITS][N_PTS];      // max_j (dot + cb), per split (ce added later)

__device__ __forceinline__ uint32_t smem_u32(const void* p) {
    uint32_t a;
    asm("{ .reg .u64 t; cvta.to.shared.u64 t, %1; cvt.u32.u64 %0, t; }" : "=r"(a) : "l"(p));
    return a;
}

#define LDMX4(r0, r1, r2, r3, a) \
    asm volatile("ldmatrix.sync.aligned.m8n8.x4.shared.b16 {%0,%1,%2,%3}, [%4];" \
        : "=r"(r0), "=r"(r1), "=r"(r2), "=r"(r3) : "r"(a))

#define MMA16816(d0,d1,d2,d3, a0,a1,a2,a3, b0,b1, c0,c1,c2,c3) \
    asm volatile("mma.sync.aligned.m16n8k16.row.col.f32.bf16.bf16.f32 " \
        "{%0,%1,%2,%3},{%4,%5,%6,%7},{%8,%9},{%10,%11,%12,%13};" \
        : "=f"(d0), "=f"(d1), "=f"(d2), "=f"(d3) \
        : "r"(a0), "r"(a1), "r"(a2), "r"(a3), "r"(b0), "r"(b1), \
          "f"(c0), "f"(c1), "f"(c2), "f"(c3))

__device__ __forceinline__ void cp16(uint32_t dst, const void* src) {
    asm volatile("cp.async.cg.shared.global [%0], [%1], 16;" :: "r"(dst), "l"(src));
}
#define CP_COMMIT() asm volatile("cp.async.commit_group;" ::: "memory")
#define CP_WAIT(n)  asm volatile("cp.async.wait_group %0;" :: "n"(n) : "memory")

// ---------------- prep: fp32 -> bf16 dense K=16 rows + fp32 constants ----------------
__global__ void kde_prep(const float* __restrict__ xe, const float* __restrict__ xb) {
    int g = blockIdx.x * blockDim.x + threadIdx.x;       // 0..32767
    bool is_e = g < N_PTS;
    int row = is_e ? g : g - N_PTS;
    const float* src = (is_e ? xe : xb) + (size_t)row * D;

    float n2 = 0.f;
    __nv_bfloat16 r[16];
    #pragma unroll
    for (int q = 0; q < 4; q++) {
        float4 t = ((const float4*)src)[q];
        n2 += t.x*t.x + t.y*t.y + t.z*t.z + t.w*t.w;
        float sc = is_e ? 100.f : 1.f;
        r[4*q+0] = __float2bfloat16(sc * t.x);
        r[4*q+1] = __float2bfloat16(sc * t.y);
        r[4*q+2] = __float2bfloat16(sc * t.z);
        r[4*q+3] = __float2bfloat16(sc * t.w);
    }
    if (is_e) g_ce[row] = T1_CONST - 50.f * n2;
    else      g_cb[row] = -50.f * n2;

    uint4* dst = (uint4*)((is_e ? g_A : g_B) + (size_t)row * ROWB);
    const uint4* rp = (const uint4*)r;
    dst[0] = rp[0];
    dst[1] = rp[1];
}

// ---------------- main: K=16 HMMA GEMM, epilogue adds cb and maxes ----------------
// grid = 1024: blockIdx.x = mblk*8 + split. CTA = 128 thr (4 warps), warp owns m32.
__global__ void __launch_bounds__(128) kde_main() {
    __shared__ __align__(16) unsigned char sA[128 * SROWB];
    __shared__ __align__(16) unsigned char sB[2][BT * SROWB];
    __shared__ __align__(16) float scb[2][BT];

    const int tid = threadIdx.x, w = tid >> 5, lane = tid & 31;
    const int mblk = blockIdx.x >> 3, split = blockIdx.x & 7;

    const unsigned char* Ag = g_A + (size_t)mblk * 128 * ROWB;
    const unsigned char* Bg = g_B + (size_t)split * (N_PTS / NSPLITS) * ROWB;
    const float* cbg = g_cb + (size_t)split * (N_PTS / NSPLITS);

    const uint32_t sA_a = smem_u32(sA);
    const uint32_t sB_a[2] = { smem_u32(sB[0]), smem_u32(sB[1]) };
    const uint32_t scb_a[2] = { smem_u32(scb[0]), smem_u32(scb[1]) };

    // Prologue (group 0): A tile + B tile 0 + cb tile 0 (64B rows -> 48B smem stride).
    {
        #pragma unroll
        for (int k = 0; k < 2; k++) {
            int i = tid + k * 128;           // 256 chunks of 16B
            uint32_t row = i >> 1, c = i & 1;
            uint32_t soff = row * SROWB + c * 16;
            cp16(sA_a + soff,    Ag + (size_t)i * 16);
            cp16(sB_a[0] + soff, Bg + (size_t)i * 16);
        }
        if (tid < 32) cp16(scb_a[0] + tid * 16, cbg + tid * 4);
        CP_COMMIT();
        CP_WAIT(0);
    }
    __syncthreads();

    // A fragments (2 m16-tiles, K=16), loaded once per warp.
    uint32_t af[2][4];
    {
        int grp = lane >> 3;
        int arow = ((grp & 1) << 3) + (lane & 7);      // 0..15 within m16 tile
        int akb  = (grp >> 1) << 4;                    // 0 or 16 bytes
        #pragma unroll
        for (int mt = 0; mt < 2; mt++) {
            uint32_t addr = sA_a + (uint32_t)(w * 32 + mt * 16 + arow) * SROWB + (uint32_t)akb;
            LDMX4(af[mt][0], af[mt][1], af[mt][2], af[mt][3], addr);
        }
    }

    // B ldmatrix: one x4 covers 16 cols x K16: lanes 0-15 -> cols 0-7 (chunks 0,16),
    // lanes 16-31 -> cols 8-15. regs {b0,b1} = cols 0-7 frag, {b2,b3} = cols 8-15.
    const uint32_t boff = ((uint32_t)(((lane >> 4) << 3) + (lane & 7))) * SROWB
                        + (uint32_t)(((lane >> 3) & 1) << 4);
    const uint32_t cb_off = (uint32_t)((lane & 3) << 3);   // byte offset of float2
    const float zf = 0.0f;
    float rm[4] = {-3.0e38f, -3.0e38f, -3.0e38f, -3.0e38f};

    for (int t = 0; t < TILES_PER_SPLIT; t++) {
        const int cur = t & 1;

        if (t + 1 < TILES_PER_SPLIT) {
            const unsigned char* src = Bg + (size_t)(t + 1) * BT * ROWB;
            #pragma unroll
            for (int k = 0; k < 2; k++) {
                int i = tid + k * 128;
                uint32_t row = i >> 1, c = i & 1;
                cp16(sB_a[cur ^ 1] + row * SROWB + c * 16, src + (size_t)i * 16);
            }
            if (tid < 32) cp16(scb_a[cur ^ 1] + tid * 16, cbg + (size_t)(t + 1) * BT + tid * 4);
            CP_COMMIT();
            CP_WAIT(1);          // group t (current tile) complete
        } else {
            CP_WAIT(0);
        }
        __syncthreads();

        const uint32_t bbase = sB_a[cur] + boff;
        const float* cbt = (const float*)(scb[cur]);
        #pragma unroll
        for (int n16 = 0; n16 < 8; n16++) {
            uint32_t b0, b1, b2, b3;
            LDMX4(b0, b1, b2, b3, bbase + (uint32_t)n16 * (16 * SROWB));
            // cb pairs for this thread's columns in the two col-groups
            float2 cA = *(const float2*)((const char*)cbt + n16 * 64 + cb_off);
            float2 cB = *(const float2*)((const char*)cbt + n16 * 64 + 32 + cb_off);
            #pragma unroll
            for (int mt = 0; mt < 2; mt++) {
                float d0, d1, d2, d3, e0, e1, e2, e3;
                MMA16816(d0, d1, d2, d3,
                         af[mt][0], af[mt][1], af[mt][2], af[mt][3],
                         b0, b1, zf, zf, zf, zf);
                MMA16816(e0, e1, e2, e3,
                         af[mt][0], af[mt][1], af[mt][2], af[mt][3],
                         b2, b3, zf, zf, zf, zf);
                // row r = lane>>2 (+16*mt): d0,d1 cols cA; e0,e1 cols cB
                float s0 = fmaxf(d0 + cA.x, d1 + cA.y);
                float s1 = fmaxf(e0 + cB.x, e1 + cB.y);
                rm[mt * 2 + 0] = fmaxf(rm[mt * 2 + 0], fmaxf(s0, s1));
                // row r+8: d2,d3 / e2,e3
                float s2 = fmaxf(d2 + cA.x, d3 + cA.y);
                float s3 = fmaxf(e2 + cB.x, e3 + cB.y);
                rm[mt * 2 + 1] = fmaxf(rm[mt * 2 + 1], fmaxf(s2, s3));
            }
        }
        __syncthreads();   // compute on buf[cur] done before group t+2 overwrites it
    }

    // reduce across the 4-lane quad (cols), then store per-row maxes (ce added later)
    #pragma unroll
    for (int i = 0; i < 4; i++) {
        rm[i] = fmaxf(rm[i], __shfl_xor_sync(0xffffffffu, rm[i], 1));
        rm[i] = fmaxf(rm[i], __shfl_xor_sync(0xffffffffu, rm[i], 2));
    }
    if ((lane & 3) == 0) {
        int q = lane >> 2;
        int base = mblk * 128 + w * 32;
        g_rowmax[split][base + q]      = rm[0];   // mt0, row q
        g_rowmax[split][base + q + 8]  = rm[1];   // mt0, row q+8
        g_rowmax[split][base + q + 16] = rm[2];   // mt1, row q+16
        g_rowmax[split][base + q + 24] = rm[3];   // mt1, row q+24
    }
}

// ---------------- final: exact recompute for flagged rows, const for the rest ----
__global__ void kde_final(const float* __restrict__ xe, const float* __restrict__ xb,
                          float* __restrict__ out) {
    __shared__ int s_list[128];
    __shared__ int s_cnt;
    __shared__ float s_red[128];
    __shared__ float s_e[D];

    int tid = threadIdx.x;
    int row = blockIdx.x * 128 + tid;
    if (tid == 0) s_cnt = 0;
    __syncthreads();

    float mv = -3.0e38f;
    #pragma unroll
    for (int k = 0; k < NSPLITS; k++) mv = fmaxf(mv, g_rowmax[k][row]);
    mv += g_ce[row];
    if (mv > FLAG_THRESH) {
        int p = atomicAdd(&s_cnt, 1);
        s_list[p] = row;
    } else {
        out[row] = LOG_EPS;
    }
    __syncthreads();

    for (int f = 0; f < s_cnt; f++) {
        int i = s_list[f];
        if (tid < D) s_e[tid] = xe[(size_t)i * D + tid];
        __syncthreads();
        float e[D];
        #pragma unroll
        for (int k = 0; k < D; k++) e[k] = s_e[k];
        float acc = 0.f;
        for (int j = tid; j < N_PTS; j += 128) {
            const float4* bp = (const float4*)(xb + (size_t)j * D);
            float sq = 0.f;
            #pragma unroll
            for (int q = 0; q < 4; q++) {
                float4 b = bp[q];
                float d0 = e[4*q+0] - b.x, d1 = e[4*q+1] - b.y;
                float d2 = e[4*q+2] - b.z, d3 = e[4*q+3] - b.w;
                sq += d0*d0 + d1*d1 + d2*d2 + d3*d3;
            }
            float s = T1_CONST - 50.f * sq;
            if (s > -87.0f) acc += __expf(s);
        }
        s_red[tid] = acc;
        __syncthreads();
        for (int st = 64; st > 0; st >>= 1) {
            if (tid < st) s_red[tid] += s_red[tid + st];
            __syncthreads();
        }
        if (tid == 0) out[i] = logf(1e-8f + s_red[0] * (1.0f / (float)N_PTS));
        __syncthreads();
    }
}

extern "C" void kernel_launch(void* const* d_in, const int* in_sizes, int n_in,
                              void* d_out, int out_size) {
    const float* x_eval = (const float*)d_in[0];
    const float* x_base = (const float*)d_in[1];
    float* out = (float*)d_out;

    kde_prep<<<(2 * N_PTS) / 256, 256>>>(x_eval, x_base);
    kde_main<<<128 * NSPLITS, 128>>>();
    kde_final<<<N_PTS / 128, 128>>>(x_eval, x_base, out);
}

// round 13
// speedup vs baseline: 6.9169x; 1.0516x over previous
#include <cuda_runtime.h>
#include <cuda_bf16.h>
#include <math.h>
#include <cstdint>

#define N_PTS 16384
#define D 16
// t1 = -0.5*D*log(2*pi) - log(0.1)
#define T1_CONST (-12.400431438280716f)
#define LOG_EPS  (-18.420680743952367f)   // logf(1e-8)
#define FLAG_THRESH (-45.0f)

#define ROWB 32                 // dense bf16 row bytes in gmem (16 bf16, K=16 exactly)
#define SROWB 48                // smem row stride: 16B-aligned, 12-bank step -> conflict-free ldmatrix
#define BT 128                  // base rows per smem tile
#define NSPLITS 8
#define TILES_PER_SPLIT ((N_PTS / NSPLITS) / BT)   // 16

// Scratch (no device allocation allowed)
__device__ unsigned char g_A[N_PTS * ROWB];     // eval rows: bf16(100*e)
__device__ unsigned char g_B[N_PTS * ROWB];     // base rows: bf16(b)
__device__ float g_ce[N_PTS];                   // t1 - 50||e||^2   (fp32 exact)
__device__ float g_cb[N_PTS];                   // -50||b||^2       (fp32 exact)
__device__ float g_rowmax[NSPLITS][N_PTS];      // max_j (dot + cb), per split (ce added later)

__device__ __forceinline__ uint32_t smem_u32(const void* p) {
    uint32_t a;
    asm("{ .reg .u64 t; cvta.to.shared.u64 t, %1; cvt.u32.u64 %0, t; }" : "=r"(a) : "l"(p));
    return a;
}

#define LDMX4(r0, r1, r2, r3, a) \
    asm volatile("ldmatrix.sync.aligned.m8n8.x4.shared.b16 {%0,%1,%2,%3}, [%4];" \
        : "=r"(r0), "=r"(r1), "=r"(r2), "=r"(r3) : "r"(a))

#define MMA16816(d0,d1,d2,d3, a0,a1,a2,a3, b0,b1, c0,c1,c2,c3) \
    asm volatile("mma.sync.aligned.m16n8k16.row.col.f32.bf16.bf16.f32 " \
        "{%0,%1,%2,%3},{%4,%5,%6,%7},{%8,%9},{%10,%11,%12,%13};" \
        : "=f"(d0), "=f"(d1), "=f"(d2), "=f"(d3) \
        : "r"(a0), "r"(a1), "r"(a2), "r"(a3), "r"(b0), "r"(b1), \
          "f"(c0), "f"(c1), "f"(c2), "f"(c3))

__device__ __forceinline__ void cp16(uint32_t dst, const void* src) {
    asm volatile("cp.async.cg.shared.global [%0], [%1], 16;" :: "r"(dst), "l"(src));
}
#define CP_COMMIT() asm volatile("cp.async.commit_group;" ::: "memory")
#define CP_WAIT(n)  asm volatile("cp.async.wait_group %0;" :: "n"(n) : "memory")

// ---------------- prep: fp32 -> bf16 dense K=16 rows + fp32 constants ----------------
__global__ void kde_prep(const float* __restrict__ xe, const float* __restrict__ xb) {
    int g = blockIdx.x * blockDim.x + threadIdx.x;       // 0..32767
    bool is_e = g < N_PTS;
    int row = is_e ? g : g - N_PTS;
    const float* src = (is_e ? xe : xb) + (size_t)row * D;

    float n2 = 0.f;
    __nv_bfloat16 r[16];
    #pragma unroll
    for (int q = 0; q < 4; q++) {
        float4 t = ((const float4*)src)[q];
        n2 += t.x*t.x + t.y*t.y + t.z*t.z + t.w*t.w;
        float sc = is_e ? 100.f : 1.f;
        r[4*q+0] = __float2bfloat16(sc * t.x);
        r[4*q+1] = __float2bfloat16(sc * t.y);
        r[4*q+2] = __float2bfloat16(sc * t.z);
        r[4*q+3] = __float2bfloat16(sc * t.w);
    }
    if (is_e) g_ce[row] = T1_CONST - 50.f * n2;
    else      g_cb[row] = -50.f * n2;

    uint4* dst = (uint4*)((is_e ? g_A : g_B) + (size_t)row * ROWB);
    const uint4* rp = (const uint4*)r;
    dst[0] = rp[0];
    dst[1] = rp[1];
}

// ---------------- main: K=16 HMMA GEMM, cb folded into the MMA c-operand ----------------
// grid = 1024: blockIdx.x = mblk*8 + split. CTA = 128 thr (4 warps), warp owns m32.
// c fragment layout: {c0,c1} = row r cols (c,c+1); {c2,c3} = row r+8 same cols.
// cb is column-only => c = {cb0, cb1, cb0, cb1} makes the MMA produce dot+cb directly.
__global__ void __launch_bounds__(128) kde_main() {
    __shared__ __align__(16) unsigned char sA[128 * SROWB];
    __shared__ __align__(16) unsigned char sB[2][BT * SROWB];
    __shared__ __align__(16) float scb[2][BT];

    const int tid = threadIdx.x, w = tid >> 5, lane = tid & 31;
    const int mblk = blockIdx.x >> 3, split = blockIdx.x & 7;

    const unsigned char* Ag = g_A + (size_t)mblk * 128 * ROWB;
    const unsigned char* Bg = g_B + (size_t)split * (N_PTS / NSPLITS) * ROWB;
    const float* cbg = g_cb + (size_t)split * (N_PTS / NSPLITS);

    const uint32_t sA_a = smem_u32(sA);
    const uint32_t sB_a[2] = { smem_u32(sB[0]), smem_u32(sB[1]) };
    const uint32_t scb_a[2] = { smem_u32(scb[0]), smem_u32(scb[1]) };

    // Prologue (group 0): A tile + B tile 0 + cb tile 0 (32B rows -> 48B smem stride).
    {
        #pragma unroll
        for (int k = 0; k < 2; k++) {
            int i = tid + k * 128;           // 256 chunks of 16B
            uint32_t row = i >> 1, c = i & 1;
            uint32_t soff = row * SROWB + c * 16;
            cp16(sA_a + soff,    Ag + (size_t)i * 16);
            cp16(sB_a[0] + soff, Bg + (size_t)i * 16);
        }
        if (tid < 32) cp16(scb_a[0] + tid * 16, cbg + tid * 4);
        CP_COMMIT();
        CP_WAIT(0);
    }
    __syncthreads();

    // A fragments (2 m16-tiles, K=16), loaded once per warp.
    uint32_t af[2][4];
    {
        int grp = lane >> 3;
        int arow = ((grp & 1) << 3) + (lane & 7);      // 0..15 within m16 tile
        int akb  = (grp >> 1) << 4;                    // 0 or 16 bytes
        #pragma unroll
        for (int mt = 0; mt < 2; mt++) {
            uint32_t addr = sA_a + (uint32_t)(w * 32 + mt * 16 + arow) * SROWB + (uint32_t)akb;
            LDMX4(af[mt][0], af[mt][1], af[mt][2], af[mt][3], addr);
        }
    }

    // B ldmatrix: one x4 covers 16 cols x K16: lanes 0-15 -> cols 0-7 (chunks 0,16),
    // lanes 16-31 -> cols 8-15. regs {b0,b1} = cols 0-7 frag, {b2,b3} = cols 8-15.
    const uint32_t boff = ((uint32_t)(((lane >> 4) << 3) + (lane & 7))) * SROWB
                        + (uint32_t)(((lane >> 3) & 1) << 4);
    const uint32_t cb_off = (uint32_t)((lane & 3) << 3);   // byte offset of float2
    float rm[4] = {-3.0e38f, -3.0e38f, -3.0e38f, -3.0e38f};

    for (int t = 0; t < TILES_PER_SPLIT; t++) {
        const int cur = t & 1;

        if (t + 1 < TILES_PER_SPLIT) {
            const unsigned char* src = Bg + (size_t)(t + 1) * BT * ROWB;
            #pragma unroll
            for (int k = 0; k < 2; k++) {
                int i = tid + k * 128;
                uint32_t row = i >> 1, c = i & 1;
                cp16(sB_a[cur ^ 1] + row * SROWB + c * 16, src + (size_t)i * 16);
            }
            if (tid < 32) cp16(scb_a[cur ^ 1] + tid * 16, cbg + (size_t)(t + 1) * BT + tid * 4);
            CP_COMMIT();
            CP_WAIT(1);          // group t (current tile) complete
        } else {
            CP_WAIT(0);
        }
        __syncthreads();

        const uint32_t bbase = sB_a[cur] + boff;
        const float* cbt = (const float*)(scb[cur]);
        #pragma unroll
        for (int n16 = 0; n16 < 8; n16++) {
            uint32_t b0, b1, b2, b3;
            LDMX4(b0, b1, b2, b3, bbase + (uint32_t)n16 * (16 * SROWB));
            // cb pairs for this thread's columns in the two col-groups
            float2 cA = *(const float2*)((const char*)cbt + n16 * 64 + cb_off);
            float2 cB = *(const float2*)((const char*)cbt + n16 * 64 + 32 + cb_off);
            #pragma unroll
            for (int mt = 0; mt < 2; mt++) {
                float d0, d1, d2, d3, e0, e1, e2, e3;
                // c-operand = cb per column: MMA emits dot + cb directly (no scalar FADDs)
                MMA16816(d0, d1, d2, d3,
                         af[mt][0], af[mt][1], af[mt][2], af[mt][3],
                         b0, b1, cA.x, cA.y, cA.x, cA.y);
                MMA16816(e0, e1, e2, e3,
                         af[mt][0], af[mt][1], af[mt][2], af[mt][3],
                         b2, b3, cB.x, cB.y, cB.x, cB.y);
                // row r (= lane>>2 + 16*mt): d0,d1,e0,e1 ; row r+8: d2,d3,e2,e3
                rm[mt * 2 + 0] = fmaxf(rm[mt * 2 + 0], fmaxf(fmaxf(d0, d1), fmaxf(e0, e1)));
                rm[mt * 2 + 1] = fmaxf(rm[mt * 2 + 1], fmaxf(fmaxf(d2, d3), fmaxf(e2, e3)));
            }
        }
        __syncthreads();   // compute on buf[cur] done before group t+2 overwrites it
    }

    // reduce across the 4-lane quad (cols), then store per-row maxes (ce added later)
    #pragma unroll
    for (int i = 0; i < 4; i++) {
        rm[i] = fmaxf(rm[i], __shfl_xor_sync(0xffffffffu, rm[i], 1));
        rm[i] = fmaxf(rm[i], __shfl_xor_sync(0xffffffffu, rm[i], 2));
    }
    if ((lane & 3) == 0) {
        int q = lane >> 2;
        int base = mblk * 128 + w * 32;
        g_rowmax[split][base + q]      = rm[0];   // mt0, row q
        g_rowmax[split][base + q + 8]  = rm[1];   // mt0, row q+8
        g_rowmax[split][base + q + 16] = rm[2];   // mt1, row q+16
        g_rowmax[split][base + q + 24] = rm[3];   // mt1, row q+24
    }
}

// ---------------- final: exact recompute for flagged rows, const for the rest ----
__global__ void kde_final(const float* __restrict__ xe, const float* __restrict__ xb,
                          float* __restrict__ out) {
    __shared__ int s_list[128];
    __shared__ int s_cnt;
    __shared__ float s_red[128];
    __shared__ float s_e[D];

    int tid = threadIdx.x;
    int row = blockIdx.x * 128 + tid;
    if (tid == 0) s_cnt = 0;
    __syncthreads();

    float mv = -3.0e38f;
    #pragma unroll
    for (int k = 0; k < NSPLITS; k++) mv = fmaxf(mv, g_rowmax[k][row]);
    mv += g_ce[row];
    if (mv > FLAG_THRESH) {
        int p = atomicAdd(&s_cnt, 1);
        s_list[p] = row;
    } else {
        out[row] = LOG_EPS;
    }
    __syncthreads();

    for (int f = 0; f < s_cnt; f++) {
        int i = s_list[f];
        if (tid < D) s_e[tid] = xe[(size_t)i * D + tid];
        __syncthreads();
        float e[D];
        #pragma unroll
        for (int k = 0; k < D; k++) e[k] = s_e[k];
        float acc = 0.f;
        for (int j = tid; j < N_PTS; j += 128) {
            const float4* bp = (const float4*)(xb + (size_t)j * D);
            float sq = 0.f;
            #pragma unroll
            for (int q = 0; q < 4; q++) {
                float4 b = bp[q];
                float d0 = e[4*q+0] - b.x, d1 = e[4*q+1] - b.y;
                float d2 = e[4*q+2] - b.z, d3 = e[4*q+3] - b.w;
                sq += d0*d0 + d1*d1 + d2*d2 + d3*d3;
            }
            float s = T1_CONST - 50.f * sq;
            if (s > -87.0f) acc += __expf(s);
        }
        s_red[tid] = acc;
        __syncthreads();
        for (int st = 64; st > 0; st >>= 1) {
            if (tid < st) s_red[tid] += s_red[tid + st];
            __syncthreads();
        }
        if (tid == 0) out[i] = logf(1e-8f + s_red[0] * (1.0f / (float)N_PTS));
        __syncthreads();
    }
}

extern "C" void kernel_launch(void* const* d_in, const int* in_sizes, int n_in,
                              void* d_out, int out_size) {
    const float* x_eval = (const float*)d_in[0];
    const float* x_base = (const float*)d_in[1];
    float* out = (float*)d_out;

    kde_prep<<<(2 * N_PTS) / 256, 256>>>(x_eval, x_base);
    kde_main<<<128 * NSPLITS, 128>>>();
    kde_final<<<N_PTS / 128, 128>>>(x_eval, x_base, out);
}

// round 14
// speedup vs baseline: 8.2471x; 1.1923x over previous
#include <cuda_runtime.h>
#include <cuda_fp16.h>
#include <math.h>
#include <cstdint>

#define N_PTS 16384
#define D 16
// t1 = -0.5*D*log(2*pi) - log(0.1)
#define T1_CONST (-12.400431438280716f)
#define LOG_EPS  (-18.420680743952367f)   // logf(1e-8)
#define FLAG_THRESH (-45.0f)

#define ROWB 32                 // dense f16 row bytes in gmem (16 halves, K=16 exactly)
#define SROWB 48                // smem row stride: 16B-aligned, conflict-free ldmatrix
#define BT 128                  // base rows per smem tile
#define NSTAGE 3
#define NSPLITS 8
#define TILES_PER_SPLIT ((N_PTS / NSPLITS) / BT)   // 16

// Scratch (no device allocation allowed)
__device__ unsigned char g_A[N_PTS * ROWB];     // eval rows: f16(100*e)
__device__ unsigned char g_B[N_PTS * ROWB];     // base rows: f16(b)
__device__ float  g_ce[N_PTS];                  // t1 - 50||e||^2   (fp32 exact)
__device__ __half g_cbh[N_PTS];                 // -50||b||^2       (f16, screen only)
__device__ float  g_rowmax[NSPLITS][N_PTS];     // max_j (dot + cb), per split (ce added later)

__device__ __forceinline__ uint32_t smem_u32(const void* p) {
    uint32_t a;
    asm("{ .reg .u64 t; cvta.to.shared.u64 t, %1; cvt.u32.u64 %0, t; }" : "=r"(a) : "l"(p));
    return a;
}

#define LDMX4(r0, r1, r2, r3, a) \
    asm volatile("ldmatrix.sync.aligned.m8n8.x4.shared.b16 {%0,%1,%2,%3}, [%4];" \
        : "=r"(r0), "=r"(r1), "=r"(r2), "=r"(r3) : "r"(a))

// f16-accumulate HMMA: D,C are 2 packed regs ({row r, cols c,c+1}, {row r+8, same cols})
#define MMA16816H(d0,d1, a0,a1,a2,a3, b0,b1, c0,c1) \
    asm volatile("mma.sync.aligned.m16n8k16.row.col.f16.f16.f16.f16 " \
        "{%0,%1},{%2,%3,%4,%5},{%6,%7},{%8,%9};" \
        : "=r"(d0), "=r"(d1) \
        : "r"(a0), "r"(a1), "r"(a2), "r"(a3), "r"(b0), "r"(b1), "r"(c0), "r"(c1))

#define HMAX2(d, a, b) \
    asm("max.f16x2 %0, %1, %2;" : "=r"(d) : "r"(a), "r"(b))

__device__ __forceinline__ void cp16(uint32_t dst, const void* src) {
    asm volatile("cp.async.cg.shared.global [%0], [%1], 16;" :: "r"(dst), "l"(src));
}
#define CP_COMMIT() asm volatile("cp.async.commit_group;" ::: "memory")
#define CP_WAIT(n)  asm volatile("cp.async.wait_group %0;" :: "n"(n) : "memory")

// ---------------- prep: fp32 -> f16 dense K=16 rows + constants ----------------
__global__ void kde_prep(const float* __restrict__ xe, const float* __restrict__ xb) {
    int g = blockIdx.x * blockDim.x + threadIdx.x;       // 0..32767
    bool is_e = g < N_PTS;
    int row = is_e ? g : g - N_PTS;
    const float* src = (is_e ? xe : xb) + (size_t)row * D;

    float n2 = 0.f;
    __half r[16];
    #pragma unroll
    for (int q = 0; q < 4; q++) {
        float4 t = ((const float4*)src)[q];
        n2 += t.x*t.x + t.y*t.y + t.z*t.z + t.w*t.w;
        float sc = is_e ? 100.f : 1.f;
        r[4*q+0] = __float2half(sc * t.x);
        r[4*q+1] = __float2half(sc * t.y);
        r[4*q+2] = __float2half(sc * t.z);
        r[4*q+3] = __float2half(sc * t.w);
    }
    if (is_e) g_ce[row] = T1_CONST - 50.f * n2;
    else      g_cbh[row] = __float2half(-50.f * n2);

    uint4* dst = (uint4*)((is_e ? g_A : g_B) + (size_t)row * ROWB);
    const uint4* rp = (const uint4*)r;
    dst[0] = rp[0];
    dst[1] = rp[1];
}

// ---------------- main: f16 HMMA GEMM, cb in packed c-operand, HMAX2 epilogue ------
// grid = 1024: blockIdx.x = mblk*8 + split. CTA = 128 thr (4 warps), warp owns m32.
// 3-stage cp.async ring, ONE __syncthreads per tile.
__global__ void __launch_bounds__(128) kde_main() {
    __shared__ __align__(16) unsigned char sA[128 * SROWB];
    __shared__ __align__(16) unsigned char sB[NSTAGE][BT * SROWB];
    __shared__ __align__(16) __half scb[NSTAGE][BT];

    const int tid = threadIdx.x, w = tid >> 5, lane = tid & 31;
    const int mblk = blockIdx.x >> 3, split = blockIdx.x & 7;

    const unsigned char* Ag = g_A + (size_t)mblk * 128 * ROWB;
    const unsigned char* Bg = g_B + (size_t)split * (N_PTS / NSPLITS) * ROWB;
    const __half* cbg = g_cbh + (size_t)split * (N_PTS / NSPLITS);

    const uint32_t sA_a = smem_u32(sA);
    uint32_t sB_a[NSTAGE], scb_a[NSTAGE];
    #pragma unroll
    for (int s = 0; s < NSTAGE; s++) { sB_a[s] = smem_u32(sB[s]); scb_a[s] = smem_u32(scb[s]); }

    // copy helper: tile -> stage buffer (32B rows -> 48B smem stride)
    auto issue_tile = [&](int t, int s) {
        const unsigned char* src = Bg + (size_t)t * BT * ROWB;
        #pragma unroll
        for (int k = 0; k < 2; k++) {
            int i = tid + k * 128;           // 256 chunks of 16B
            uint32_t row = i >> 1, c = i & 1;
            cp16(sB_a[s] + row * SROWB + c * 16, src + (size_t)i * 16);
        }
        if (tid < 16) cp16(scb_a[s] + tid * 16, cbg + (size_t)t * BT + tid * 8);
    };

    // Prologue: group0 = A + tile0, group1 = tile1.
    {
        #pragma unroll
        for (int k = 0; k < 2; k++) {
            int i = tid + k * 128;
            uint32_t row = i >> 1, c = i & 1;
            cp16(sA_a + row * SROWB + c * 16, Ag + (size_t)i * 16);
        }
        issue_tile(0, 0);
        CP_COMMIT();
        issue_tile(1, 1);
        CP_COMMIT();
        CP_WAIT(1);              // group0 (A + tile0) complete
    }
    __syncthreads();

    // A fragments (2 m16-tiles, K=16), loaded once per warp.
    uint32_t af[2][4];
    {
        int grp = lane >> 3;
        int arow = ((grp & 1) << 3) + (lane & 7);      // 0..15 within m16 tile
        int akb  = (grp >> 1) << 4;                    // 0 or 16 bytes
        #pragma unroll
        for (int mt = 0; mt < 2; mt++) {
            uint32_t addr = sA_a + (uint32_t)(w * 32 + mt * 16 + arow) * SROWB + (uint32_t)akb;
            LDMX4(af[mt][0], af[mt][1], af[mt][2], af[mt][3], addr);
        }
    }

    // B ldmatrix: one x4 covers 16 cols x K16 ({b0,b1}=cols 0-7, {b2,b3}=cols 8-15).
    const uint32_t boff = ((uint32_t)(((lane >> 4) << 3) + (lane & 7))) * SROWB
                        + (uint32_t)(((lane >> 3) & 1) << 4);
    const uint32_t cb_off = (uint32_t)((lane & 3) << 2);   // byte offset of packed half2 (cols 2q,2q+1)
    const uint32_t NEG_INF2 = 0xFC00FC00u;                 // (-inf, -inf) f16x2
    uint32_t rm[4] = {NEG_INF2, NEG_INF2, NEG_INF2, NEG_INF2};

    for (int t = 0; t < TILES_PER_SPLIT; t++) {
        const int cur = t % NSTAGE;

        if (t + 1 < TILES_PER_SPLIT) { CP_WAIT(1); } else { CP_WAIT(0); }
        __syncthreads();   // tile t ready; buf (t+2)%3 free (computed at t-1, fenced here)

        const uint32_t bbase = sB_a[cur] + boff;
        const uint32_t cbase = scb_a[cur] + cb_off;
        #pragma unroll
        for (int n16 = 0; n16 < 8; n16++) {
            uint32_t b0, b1, b2, b3;
            LDMX4(b0, b1, b2, b3, bbase + (uint32_t)n16 * (16 * SROWB));
            uint32_t cA, cB;     // packed (cb_c, cb_c+1) for this thread's col pair
            asm volatile("ld.shared.b32 %0, [%1];" : "=r"(cA) : "r"(cbase + n16 * 32));
            asm volatile("ld.shared.b32 %0, [%1];" : "=r"(cB) : "r"(cbase + n16 * 32 + 16));
            #pragma unroll
            for (int mt = 0; mt < 2; mt++) {
                uint32_t d0, d1, e0, e1;
                MMA16816H(d0, d1, af[mt][0], af[mt][1], af[mt][2], af[mt][3], b0, b1, cA, cA);
                MMA16816H(e0, e1, af[mt][0], af[mt][1], af[mt][2], af[mt][3], b2, b3, cB, cB);
                uint32_t t0, t1;
                HMAX2(t0, d0, e0);                    // row r
                HMAX2(rm[mt * 2 + 0], rm[mt * 2 + 0], t0);
                HMAX2(t1, d1, e1);                    // row r+8
                HMAX2(rm[mt * 2 + 1], rm[mt * 2 + 1], t1);
            }
        }

        if (t + 2 < TILES_PER_SPLIT) {
            issue_tile(t + 2, (t + 2) % NSTAGE);
            CP_COMMIT();
        }
    }

    // reduce across the 4-lane quad (cols), then unpack and store per-row maxes
    #pragma unroll
    for (int i = 0; i < 4; i++) {
        uint32_t o;
        o = __shfl_xor_sync(0xffffffffu, rm[i], 1); HMAX2(rm[i], rm[i], o);
        o = __shfl_xor_sync(0xffffffffu, rm[i], 2); HMAX2(rm[i], rm[i], o);
    }
    if ((lane & 3) == 0) {
        int q = lane >> 2;
        int base = mblk * 128 + w * 32;
        #pragma unroll
        for (int i = 0; i < 4; i++) {
            __half2 h = *(__half2*)&rm[i];
            float m = fmaxf(__half2float(__low2half(h)), __half2float(__high2half(h)));
            int roff = (i & 1) * 8 + (i >> 1) * 16;      // rm: {mt0 r, mt0 r+8, mt1 r+16, mt1 r+24}
            g_rowmax[split][base + q + roff] = m;
        }
    }
}

// ---------------- final: exact recompute for flagged rows, const for the rest ----
__global__ void kde_final(const float* __restrict__ xe, const float* __restrict__ xb,
                          float* __restrict__ out) {
    __shared__ int s_list[128];
    __shared__ int s_cnt;
    __shared__ float s_red[128];
    __shared__ float s_e[D];

    int tid = threadIdx.x;
    int row = blockIdx.x * 128 + tid;
    if (tid == 0) s_cnt = 0;
    __syncthreads();

    float mv = -3.0e38f;
    #pragma unroll
    for (int k = 0; k < NSPLITS; k++) mv = fmaxf(mv, g_rowmax[k][row]);
    mv += g_ce[row];
    if (mv > FLAG_THRESH) {
        int p = atomicAdd(&s_cnt, 1);
        s_list[p] = row;
    } else {
        out[row] = LOG_EPS;
    }
    __syncthreads();

    for (int f = 0; f < s_cnt; f++) {
        int i = s_list[f];
        if (tid < D) s_e[tid] = xe[(size_t)i * D + tid];
        __syncthreads();
        float e[D];
        #pragma unroll
        for (int k = 0; k < D; k++) e[k] = s_e[k];
        float acc = 0.f;
        for (int j = tid; j < N_PTS; j += 128) {
            const float4* bp = (const float4*)(xb + (size_t)j * D);
            float sq = 0.f;
            #pragma unroll
            for (int q = 0; q < 4; q++) {
                float4 b = bp[q];
                float d0 = e[4*q+0] - b.x, d1 = e[4*q+1] - b.y;
                float d2 = e[4*q+2] - b.z, d3 = e[4*q+3] - b.w;
                sq += d0*d0 + d1*d1 + d2*d2 + d3*d3;
            }
            float s = T1_CONST - 50.f * sq;
            if (s > -87.0f) acc += __expf(s);
        }
        s_red[tid] = acc;
        __syncthreads();
        for (int st = 64; st > 0; st >>= 1) {
            if (tid < st) s_red[tid] += s_red[tid + st];
            __syncthreads();
        }
        if (tid == 0) out[i] = logf(1e-8f + s_red[0] * (1.0f / (float)N_PTS));
        __syncthreads();
    }
}

extern "C" void kernel_launch(void* const* d_in, const int* in_sizes, int n_in,
                              void* d_out, int out_size) {
    const float* x_eval = (const float*)d_in[0];
    const float* x_base = (const float*)d_in[1];
    float* out = (float*)d_out;

    kde_prep<<<(2 * N_PTS) / 256, 256>>>(x_eval, x_base);
    kde_main<<<128 * NSPLITS, 128>>>();
    kde_final<<<N_PTS / 128, 128>>>(x_eval, x_base, out);
}